// round 13
// baseline (speedup 1.0000x reference)
#include <cuda_runtime.h>
#include <cuda_fp16.h>
#include <math.h>
#include <stdint.h>

// Problem constants
#define NU 100000
#define NI 20000
#define ND 64
#define NH 128
#define NB 64

// Output layout (flattened concat of the returned tuple)
#define OFF_LIKES 0
#define OFF_SIM   1280000
#define OFF_RATED 1284096
#define OFF_POP   2564096

#define N_WORK 20157        // 20000 head tiles + 157 popular tiles
#define GRID_MAIN 148       // 1 CTA of 512 threads per SM, one wave

// Scratch (device globals — no allocation allowed)
__device__ __half g_au16[2][NB * NH];   // per-head: fp16(eu@Wu + b0)
__device__ __half g_C16[2][NI * NH];    // per-head: fp16(ei@Wi)
__device__ __half g_Cp16[NI * NH];      // popular: fp16(relu(ei@pW0 + pb0))
__device__ __half g_W16[3][NH * NH];    // W1 per head, fp16, [k][n]

// Dynamic smem (main_mma):
//   As: 2 * 128*136 half  (69632 B)
//   Bs: 128*136 half      (34816 B)
//   zpart: 2*512 float    (4096 B)
//   b1s,w2s: 128+128 float, pad
#define SMEM_BYTES (69632 + 34816 + 4096 + 512 + 512 + 16)

// ---------------------------------------------------------------------------
// PTX helpers
// ---------------------------------------------------------------------------
__device__ __forceinline__ uint32_t smem_u32(const void* p) {
    return (uint32_t)__cvta_generic_to_shared(p);
}
__device__ __forceinline__ void ldsm_x4(uint32_t* r, uint32_t addr) {
    asm volatile("ldmatrix.sync.aligned.m8n8.x4.shared.b16 {%0,%1,%2,%3}, [%4];"
        : "=r"(r[0]), "=r"(r[1]), "=r"(r[2]), "=r"(r[3]) : "r"(addr));
}
__device__ __forceinline__ void ldsm_x4_trans(uint32_t* r, uint32_t addr) {
    asm volatile("ldmatrix.sync.aligned.m8n8.x4.trans.shared.b16 {%0,%1,%2,%3}, [%4];"
        : "=r"(r[0]), "=r"(r[1]), "=r"(r[2]), "=r"(r[3]) : "r"(addr));
}
__device__ __forceinline__ void mma_fp16(float* d, const uint32_t* a,
                                         const uint32_t* b, const float* c) {
    asm volatile("mma.sync.aligned.m16n8k16.row.col.f32.f16.f16.f32 "
        "{%0,%1,%2,%3}, {%4,%5,%6,%7}, {%8,%9}, {%10,%11,%12,%13};"
        : "=f"(d[0]), "=f"(d[1]), "=f"(d[2]), "=f"(d[3])
        : "r"(a[0]), "r"(a[1]), "r"(a[2]), "r"(a[3]),
          "r"(b[0]), "r"(b[1]),
          "f"(c[0]), "f"(c[1]), "f"(c[2]), "f"(c[3]));
}
__device__ __forceinline__ __half2 u2h(uint32_t v) {
    return *reinterpret_cast<__half2*>(&v);
}
__device__ __forceinline__ uint32_t h2u(__half2 v) {
    return *reinterpret_cast<uint32_t*>(&v);
}
// On-demand 3-way select (params live in constant bank; no persistent regs)
__device__ __forceinline__ const float* sel3(int h, const float* a,
                                             const float* b, const float* c) {
    return (h == 0) ? a : ((h == 1) ? b : c);
}

// ---------------------------------------------------------------------------
// prep_all: heterogeneous blocks (unchanged).
// ---------------------------------------------------------------------------
__global__ __launch_bounds__(256) void prep_all(
    const int* __restrict__ users, const float* __restrict__ ue,
    const float* __restrict__ ie,
    const float* __restrict__ lW0, const float* __restrict__ lb0,
    const float* __restrict__ rW0, const float* __restrict__ rb0,
    const float* __restrict__ pW0, const float* __restrict__ pb0,
    const float* __restrict__ lW1, const float* __restrict__ rW1,
    const float* __restrict__ pW1,
    float* __restrict__ out_sim)
{
    __shared__ __align__(16) char pbuf[33024];
    int bx = blockIdx.x;
    int tid = threadIdx.x;

    if (bx < 939) {
        int h = bx / 313;
        int blk = bx - h * 313;
        float (*eiN)[65]  = reinterpret_cast<float(*)[65]>(pbuf);
        float (*w0s)[128] = reinterpret_cast<float(*)[128]>(pbuf + 16640);
        int i0 = blk * 64;
        int tx = tid & 15, ty = tid >> 4;

        for (int idx = tid; idx < 4096; idx += 256) {
            int it = idx >> 6, d = idx & 63;
            int i = i0 + it;
            eiN[it][d] = (i < NI) ? ie[i * ND + d] : 0.f;
        }

        const float* W0 = (h == 0) ? lW0 : (h == 1) ? rW0 : pW0;
        int roff = (h < 2) ? ND : 0;

        float acc[4][8];
#pragma unroll
        for (int i = 0; i < 4; i++)
#pragma unroll
            for (int j = 0; j < 8; j++) acc[i][j] = 0.f;

        for (int ch = 0; ch < 2; ch++) {
            __syncthreads();
            for (int idx = tid; idx < 1024; idx += 256) {
                int d = idx >> 5, c4 = (idx & 31) << 2;
                *reinterpret_cast<float4*>(&w0s[d][c4]) =
                    *reinterpret_cast<const float4*>(&W0[(roff + ch * 32 + d) * NH + c4]);
            }
            __syncthreads();
#pragma unroll 8
            for (int d = 0; d < 32; d++) {
                int dd = ch * 32 + d;
                float e0 = eiN[ty * 4 + 0][dd];
                float e1 = eiN[ty * 4 + 1][dd];
                float e2 = eiN[ty * 4 + 2][dd];
                float e3 = eiN[ty * 4 + 3][dd];
                float4 wa = *reinterpret_cast<float4*>(&w0s[d][tx * 8]);
                float4 wb = *reinterpret_cast<float4*>(&w0s[d][tx * 8 + 4]);
                float w[8] = {wa.x, wa.y, wa.z, wa.w, wb.x, wb.y, wb.z, wb.w};
#pragma unroll
                for (int j = 0; j < 8; j++) {
                    acc[0][j] += e0 * w[j];
                    acc[1][j] += e1 * w[j];
                    acc[2][j] += e2 * w[j];
                    acc[3][j] += e3 * w[j];
                }
            }
        }

        int hbase = tx * 8;
#pragma unroll
        for (int i = 0; i < 4; i++) {
            int item = i0 + ty * 4 + i;
            if (item >= NI) continue;
            float v[8];
#pragma unroll
            for (int j = 0; j < 8; j++) {
                float a = acc[i][j];
                if (h == 2) a = fmaxf(a + pb0[hbase + j], 0.f);
                v[j] = a;
            }
            __half2 h0 = __floats2half2_rn(v[0], v[1]);
            __half2 h1 = __floats2half2_rn(v[2], v[3]);
            __half2 h2c = __floats2half2_rn(v[4], v[5]);
            __half2 h3 = __floats2half2_rn(v[6], v[7]);
            uint4 pk;
            pk.x = h2u(h0); pk.y = h2u(h1); pk.z = h2u(h2c); pk.w = h2u(h3);
            __half* dst = (h < 2) ? &g_C16[h][item * NH + hbase]
                                  : &g_Cp16[item * NH + hbase];
            *reinterpret_cast<uint4*>(dst) = pk;
        }
    } else if (bx < 942) {
        float (*eu_s)[65] = reinterpret_cast<float(*)[65]>(pbuf);
        float* inv = reinterpret_cast<float*>(pbuf + 16640);
        for (int idx = tid; idx < NB * ND; idx += 256) {
            int b = idx >> 6, d = idx & 63;
            eu_s[b][d] = ue[users[b] * ND + d];
        }
        __syncthreads();
        int blk = bx - 939;
        if (blk < 2) {
            const float* W0 = (blk == 0) ? lW0 : rW0;
            const float* b0 = (blk == 0) ? lb0 : rb0;
            for (int o = tid; o < NB * NH; o += 256) {
                int b = o >> 7, h = o & 127;
                float acc = b0[h];
#pragma unroll
                for (int d = 0; d < ND; d++)
                    acc += eu_s[b][d] * W0[d * NH + h];
                g_au16[blk][o] = __float2half(acc);
            }
        } else {
            for (int b = tid; b < NB; b += 256) {
                float s = 0.f;
#pragma unroll
                for (int d = 0; d < ND; d++) { float v = eu_s[b][d]; s += v * v; }
                inv[b] = rsqrtf(fmaxf(s, 1e-12f));
            }
            __syncthreads();
            for (int o = tid; o < NB * NB; o += 256) {
                int a = o >> 6, b = o & 63;
                float s = 0.f;
#pragma unroll
                for (int d = 0; d < ND; d++)
                    s += eu_s[a][d] * eu_s[b][d];
                out_sim[o] = -(s * inv[a] * inv[b]);
            }
        }
    } else {
        int base = (bx - 942) * 1024 + tid;
#pragma unroll
        for (int j = 0; j < 4; j++) {
            int idx = base + j * 256;
            if (idx < 3 * NH * NH) {
                int h = idx / (NH * NH);
                int rem = idx - h * NH * NH;
                const float* W = (h == 0) ? lW1 : (h == 1) ? rW1 : pW1;
                g_W16[h][rem] = __float2half(W[rem]);
            }
        }
    }
}

// ---------------------------------------------------------------------------
// Work decode: tile index w -> (head, user-tile base, item base)
// ---------------------------------------------------------------------------
__device__ __forceinline__ void decode_w(int w, int& head, int& b0u, int& i0) {
    if (w < 20000) {
        head = w / 10000;
        int rem = w - head * 10000;
        b0u = (rem / 1250) * 8;
        i0 = (rem % 1250) * 16;
    } else {
        head = 2;
        b0u = 0;
        i0 = (w - 20000) * 128;
    }
}

// ---------------------------------------------------------------------------
// A-tile builder: uint4 loads, fully unrolled (4 iterations / thread @512t)
// ---------------------------------------------------------------------------
__device__ __forceinline__ void build_A(__half* __restrict__ dst, int head,
                                        int b0u, int i0, int tid)
{
    const __half2 z2 = __floats2half2_rn(0.f, 0.f);
    if (head < 2) {
#pragma unroll
        for (int it = 0; it < 4; it++) {
            int idx = tid + it * 512;
            int r = idx >> 4;
            int kc = (idx & 15) << 3;
            int b = b0u + (r & 7);
            int ii = i0 + (r >> 3);
            uint4 cv = *reinterpret_cast<const uint4*>(&g_C16[head][ii * NH + kc]);
            uint4 av = *reinterpret_cast<const uint4*>(&g_au16[head][b * NH + kc]);
            uint4 p;
            p.x = h2u(__hmax2(__hadd2(u2h(cv.x), u2h(av.x)), z2));
            p.y = h2u(__hmax2(__hadd2(u2h(cv.y), u2h(av.y)), z2));
            p.z = h2u(__hmax2(__hadd2(u2h(cv.z), u2h(av.z)), z2));
            p.w = h2u(__hmax2(__hadd2(u2h(cv.w), u2h(av.w)), z2));
            *reinterpret_cast<uint4*>(&dst[r * 136 + kc]) = p;
        }
    } else {
#pragma unroll
        for (int it = 0; it < 4; it++) {
            int idx = tid + it * 512;
            int r = idx >> 4;
            int kc = (idx & 15) << 3;
            int ii = i0 + r;
            uint4 p = (ii < NI)
                ? *reinterpret_cast<const uint4*>(&g_Cp16[ii * NH + kc])
                : make_uint4(0u, 0u, 0u, 0u);
            *reinterpret_cast<uint4*>(&dst[r * 136 + kc]) = p;
        }
    }
}

// ---------------------------------------------------------------------------
// main_mma: persistent 512-thread blocks, 16 warps as (4M x 4N), warp tile
// 32x32. B fragments register-cached across the chunk; per-tile ldsm is
// A-only. Register diet: no pointer tables (sel3 from constant bank).
// ---------------------------------------------------------------------------
__global__ __launch_bounds__(512, 1) void main_mma(
    const float* __restrict__ lb1, const float* __restrict__ lW2, const float* __restrict__ lb2,
    const float* __restrict__ rb1, const float* __restrict__ rW2, const float* __restrict__ rb2,
    const float* __restrict__ pb1, const float* __restrict__ pW2, const float* __restrict__ pb2,
    float* __restrict__ out)
{
    extern __shared__ char dynsmem[];
    __half* As = reinterpret_cast<__half*>(dynsmem);          // 2 x (128*136)
    __half* Bs = As + 2 * 128 * 136;                          // 128*136
    float* zpart = reinterpret_cast<float*>(Bs + 128 * 136);  // 2 x 512
    float* b1s = zpart + 1024;
    float* w2s = b1s + 128;

    int tid = threadIdx.x;
    int warp = tid >> 5, lane = tid & 31;
    int warpN = warp >> 2, warpM = warp & 3;
    int m_base = warpM * 32, n_base = warpN * 32;
    int bid = blockIdx.x;

    int cbase = N_WORK / GRID_MAIN;
    int crem  = N_WORK % GRID_MAIN;
    int w0 = bid * cbase + min(bid, crem);
    int w1 = w0 + cbase + (bid < crem ? 1 : 0);

    int head, b0u, i0;
    decode_w(w0, head, b0u, i0);

    // ldsm geometry
    int arow = lane & 15;
    int acol_off = (lane >> 4) << 3;
    int g = lane >> 2, tq = lane & 3;
    int bgrp = lane >> 3;
    int brow_off = ((bgrp & 1) << 3) + (lane & 7);
    int bcol_off = (bgrp >> 1) << 3;

    // ---- Load head state (Bs, b1s, w2s, b2v) ----
    float b2v = sel3(head, lb2, rb2, pb2)[0];
    {
        if (tid < 128) {
            b1s[tid] = sel3(head, lb1, rb1, pb1)[tid];
            w2s[tid] = sel3(head, lW2, rW2, pW2)[tid];
        }
        const __half* Wsrc = g_W16[head];
#pragma unroll
        for (int it = 0; it < 4; it++) {
            int idx = tid + it * 512;
            int kk = idx >> 4;
            int n8 = (idx & 15) << 3;
            uint4 v = *reinterpret_cast<const uint4*>(&Wsrc[kk * NH + n8]);
            *reinterpret_cast<uint4*>(&Bs[kk * 136 + n8]) = v;
        }
    }
    build_A(As, head, b0u, i0, tid);
    __syncthreads();

    // ---- Cache B fragments for this warp's 32 columns, all 8 k-steps ----
    uint32_t Bfrag[8][4][2];
#pragma unroll
    for (int ks = 0; ks < 8; ks++) {
        int brow = (ks << 4) + brow_off;
#pragma unroll
        for (int pr = 0; pr < 2; pr++) {
            uint32_t tmp[4];
            ldsm_x4_trans(tmp, smem_u32(&Bs[brow * 136 + n_base + (pr << 4) + bcol_off]));
            Bfrag[ks][2 * pr][0] = tmp[0]; Bfrag[ks][2 * pr][1] = tmp[1];
            Bfrag[ks][2 * pr + 1][0] = tmp[2]; Bfrag[ks][2 * pr + 1][1] = tmp[3];
        }
    }

    int p = 0;
    for (int w = w0; w < w1; w++) {
        const __half* Ab = As + p * (128 * 136);

        float acc[2][4][4];
#pragma unroll
        for (int f = 0; f < 2; f++)
#pragma unroll
            for (int g2 = 0; g2 < 4; g2++)
#pragma unroll
                for (int q = 0; q < 4; q++) acc[f][g2][q] = 0.f;

        // ---- 8 k-steps: A ldsm only, B from register cache ----
#pragma unroll
        for (int ks = 0; ks < 8; ks++) {
            int kA = (ks << 4) + acol_off;
            uint32_t afr[2][4];
#pragma unroll
            for (int f = 0; f < 2; f++)
                ldsm_x4(afr[f], smem_u32(&Ab[(m_base + f * 16 + arow) * 136 + kA]));
#pragma unroll
            for (int f = 0; f < 2; f++)
#pragma unroll
                for (int g2 = 0; g2 < 4; g2++)
                    mma_fp16(acc[f][g2], afr[f], Bfrag[ks][g2], acc[f][g2]);
        }

        // ---- Prefetch-build next A into other buffer ----
        bool have_next = (w + 1 < w1);
        int nhead = head, nb0u = b0u, ni0 = i0;
        if (have_next) {
            decode_w(w + 1, nhead, nb0u, ni0);
            build_A(As + (p ^ 1) * (128 * 136), nhead, nb0u, ni0, tid);
        }

        // ---- Epilogue partials ----
        float* zp = zpart + p * 512;
#pragma unroll
        for (int f = 0; f < 2; f++) {
            float z0 = 0.f, z1 = 0.f;
#pragma unroll
            for (int nf = 0; nf < 4; nf++) {
                int col = n_base + nf * 8 + tq * 2;
                float b10 = b1s[col], b11 = b1s[col + 1];
                float ww0 = w2s[col], ww1 = w2s[col + 1];
                z0 += fmaxf(acc[f][nf][0] + b10, 0.f) * ww0 + fmaxf(acc[f][nf][1] + b11, 0.f) * ww1;
                z1 += fmaxf(acc[f][nf][2] + b10, 0.f) * ww0 + fmaxf(acc[f][nf][3] + b11, 0.f) * ww1;
            }
            z0 += __shfl_xor_sync(0xffffffffu, z0, 1);
            z0 += __shfl_xor_sync(0xffffffffu, z0, 2);
            z1 += __shfl_xor_sync(0xffffffffu, z1, 1);
            z1 += __shfl_xor_sync(0xffffffffu, z1, 2);
            if (tq == 0) {
                zp[warpN * 128 + m_base + f * 16 + g] = z0;
                zp[warpN * 128 + m_base + f * 16 + g + 8] = z1;
            }
        }
        __syncthreads();   // zpart ready + next A ready; all MMA(w) done

        // ---- Final stores for w (overlaps next tile's MMA in other warps) ----
        if (tid < 128) {
            if (head < 2) {
                int r = ((tid & 15) << 3) | (tid >> 4);
                float z = zp[r] + zp[128 + r] + zp[256 + r] + zp[384 + r] + b2v;
                float s = 1.f / (1.f + __expf(-z));
                int b = b0u + (tid >> 4);
                int i = i0 + (tid & 15);
                out[(head ? OFF_RATED : OFF_LIKES) + b * NI + i] = s;
            } else {
                float z = zp[tid] + zp[128 + tid] + zp[256 + tid] + zp[384 + tid] + b2v;
                float s = 1.f / (1.f + __expf(-z));
                int i = i0 + tid;
                if (i < NI) out[OFF_POP + i] = s;
            }
        }

        // ---- Head boundary: reload Bs/b1s/w2s/b2v + refresh B fragment cache ----
        if (have_next && nhead != head) {
            __syncthreads();
            b2v = sel3(nhead, lb2, rb2, pb2)[0];
            if (tid < 128) {
                b1s[tid] = sel3(nhead, lb1, rb1, pb1)[tid];
                w2s[tid] = sel3(nhead, lW2, rW2, pW2)[tid];
            }
            const __half* Wsrc = g_W16[nhead];
#pragma unroll
            for (int it = 0; it < 4; it++) {
                int idx = tid + it * 512;
                int kk = idx >> 4;
                int n8 = (idx & 15) << 3;
                uint4 v = *reinterpret_cast<const uint4*>(&Wsrc[kk * NH + n8]);
                *reinterpret_cast<uint4*>(&Bs[kk * 136 + n8]) = v;
            }
            __syncthreads();
#pragma unroll
            for (int ks = 0; ks < 8; ks++) {
                int brow = (ks << 4) + brow_off;
#pragma unroll
                for (int pr = 0; pr < 2; pr++) {
                    uint32_t tmp[4];
                    ldsm_x4_trans(tmp, smem_u32(&Bs[brow * 136 + n_base + (pr << 4) + bcol_off]));
                    Bfrag[ks][2 * pr][0] = tmp[0]; Bfrag[ks][2 * pr][1] = tmp[1];
                    Bfrag[ks][2 * pr + 1][0] = tmp[2]; Bfrag[ks][2 * pr + 1][1] = tmp[3];
                }
            }
        }

        head = nhead; b0u = nb0u; i0 = ni0;
        p ^= 1;
    }
}

// ---------------------------------------------------------------------------
extern "C" void kernel_launch(void* const* d_in, const int* in_sizes, int n_in,
                              void* d_out, int out_size)
{
    const int*   users = (const int*)  d_in[0];
    const float* ue    = (const float*)d_in[1];
    const float* ie    = (const float*)d_in[2];
    const float* lW0 = (const float*)d_in[3];
    const float* lb0 = (const float*)d_in[4];
    const float* lW1 = (const float*)d_in[5];
    const float* lb1 = (const float*)d_in[6];
    const float* lW2 = (const float*)d_in[7];
    const float* lb2 = (const float*)d_in[8];
    const float* rW0 = (const float*)d_in[9];
    const float* rb0 = (const float*)d_in[10];
    const float* rW1 = (const float*)d_in[11];
    const float* rb1 = (const float*)d_in[12];
    const float* rW2 = (const float*)d_in[13];
    const float* rb2 = (const float*)d_in[14];
    const float* pW0 = (const float*)d_in[15];
    const float* pb0 = (const float*)d_in[16];
    const float* pW1 = (const float*)d_in[17];
    const float* pb1 = (const float*)d_in[18];
    const float* pW2 = (const float*)d_in[19];
    const float* pb2 = (const float*)d_in[20];
    float* out = (float*)d_out;

    cudaFuncSetAttribute(main_mma, cudaFuncAttributeMaxDynamicSharedMemorySize,
                         SMEM_BYTES);

    prep_all<<<990, 256>>>(users, ue, ie,
                           lW0, lb0, rW0, rb0, pW0, pb0,
                           lW1, rW1, pW1,
                           out + OFF_SIM);
    main_mma<<<GRID_MAIN, 512, SMEM_BYTES>>>(lb1, lW2, lb2,
                                             rb1, rW2, rb2,
                                             pb1, pW2, pb2,
                                             out);
}

// round 15
// speedup vs baseline: 1.1864x; 1.1864x over previous
#include <cuda_runtime.h>
#include <cuda_fp16.h>
#include <math.h>
#include <stdint.h>

// Problem constants
#define NU 100000
#define NI 20000
#define ND 64
#define NH 128
#define NB 64

// Output layout (flattened concat of the returned tuple)
#define OFF_LIKES 0
#define OFF_SIM   1280000
#define OFF_RATED 1284096
#define OFF_POP   2564096

#define N_WORK 20157        // 20000 head tiles + 157 popular tiles
#define GRID_MAIN 296       // 148 SMs x 2 CTAs: one wave, persistent chunks

// Scratch (device globals — no allocation allowed)
__device__ __half g_au16[2][NB * NH];   // per-head: fp16(eu@Wu + b0)
__device__ __half g_C16[2][NI * NH];    // per-head: fp16(ei@Wi)
__device__ __half g_Cp16[NI * NH];      // popular: fp16(relu(ei@pW0 + pb0))
__device__ __half g_W16[3][NH * NH];    // W1 per head, fp16, [k][n]

// Dynamic smem (main_mma):
//   As: 2 * 128*136 half  (69632 B)
//   Bs: 128*136 half      (34816 B)
//   zpart: 2*512 float    (4096 B)
//   b1s,w2s: 128+128 float, pad
#define SMEM_BYTES (69632 + 34816 + 4096 + 512 + 512 + 16)

// ---------------------------------------------------------------------------
// PTX helpers
// ---------------------------------------------------------------------------
__device__ __forceinline__ uint32_t smem_u32(const void* p) {
    return (uint32_t)__cvta_generic_to_shared(p);
}
__device__ __forceinline__ void ldsm_x4(uint32_t* r, uint32_t addr) {
    asm volatile("ldmatrix.sync.aligned.m8n8.x4.shared.b16 {%0,%1,%2,%3}, [%4];"
        : "=r"(r[0]), "=r"(r[1]), "=r"(r[2]), "=r"(r[3]) : "r"(addr));
}
__device__ __forceinline__ void ldsm_x4_trans(uint32_t* r, uint32_t addr) {
    asm volatile("ldmatrix.sync.aligned.m8n8.x4.trans.shared.b16 {%0,%1,%2,%3}, [%4];"
        : "=r"(r[0]), "=r"(r[1]), "=r"(r[2]), "=r"(r[3]) : "r"(addr));
}
__device__ __forceinline__ void mma_fp16(float* d, const uint32_t* a,
                                         const uint32_t* b, const float* c) {
    asm volatile("mma.sync.aligned.m16n8k16.row.col.f32.f16.f16.f32 "
        "{%0,%1,%2,%3}, {%4,%5,%6,%7}, {%8,%9}, {%10,%11,%12,%13};"
        : "=f"(d[0]), "=f"(d[1]), "=f"(d[2]), "=f"(d[3])
        : "r"(a[0]), "r"(a[1]), "r"(a[2]), "r"(a[3]),
          "r"(b[0]), "r"(b[1]),
          "f"(c[0]), "f"(c[1]), "f"(c[2]), "f"(c[3]));
}
__device__ __forceinline__ __half2 u2h(uint32_t v) {
    return *reinterpret_cast<__half2*>(&v);
}
__device__ __forceinline__ uint32_t h2u(__half2 v) {
    return *reinterpret_cast<uint32_t*>(&v);
}
__device__ __forceinline__ const float* sel3(int h, const float* a,
                                             const float* b, const float* c) {
    return (h == 0) ? a : ((h == 1) ? b : c);
}

// ---------------------------------------------------------------------------
// prep_all: heterogeneous blocks (unchanged).
// ---------------------------------------------------------------------------
__global__ __launch_bounds__(256) void prep_all(
    const int* __restrict__ users, const float* __restrict__ ue,
    const float* __restrict__ ie,
    const float* __restrict__ lW0, const float* __restrict__ lb0,
    const float* __restrict__ rW0, const float* __restrict__ rb0,
    const float* __restrict__ pW0, const float* __restrict__ pb0,
    const float* __restrict__ lW1, const float* __restrict__ rW1,
    const float* __restrict__ pW1,
    float* __restrict__ out_sim)
{
    __shared__ __align__(16) char pbuf[33024];
    int bx = blockIdx.x;
    int tid = threadIdx.x;

    if (bx < 939) {
        int h = bx / 313;
        int blk = bx - h * 313;
        float (*eiN)[65]  = reinterpret_cast<float(*)[65]>(pbuf);
        float (*w0s)[128] = reinterpret_cast<float(*)[128]>(pbuf + 16640);
        int i0 = blk * 64;
        int tx = tid & 15, ty = tid >> 4;

        for (int idx = tid; idx < 4096; idx += 256) {
            int it = idx >> 6, d = idx & 63;
            int i = i0 + it;
            eiN[it][d] = (i < NI) ? ie[i * ND + d] : 0.f;
        }

        const float* W0 = (h == 0) ? lW0 : (h == 1) ? rW0 : pW0;
        int roff = (h < 2) ? ND : 0;

        float acc[4][8];
#pragma unroll
        for (int i = 0; i < 4; i++)
#pragma unroll
            for (int j = 0; j < 8; j++) acc[i][j] = 0.f;

        for (int ch = 0; ch < 2; ch++) {
            __syncthreads();
            for (int idx = tid; idx < 1024; idx += 256) {
                int d = idx >> 5, c4 = (idx & 31) << 2;
                *reinterpret_cast<float4*>(&w0s[d][c4]) =
                    *reinterpret_cast<const float4*>(&W0[(roff + ch * 32 + d) * NH + c4]);
            }
            __syncthreads();
#pragma unroll 8
            for (int d = 0; d < 32; d++) {
                int dd = ch * 32 + d;
                float e0 = eiN[ty * 4 + 0][dd];
                float e1 = eiN[ty * 4 + 1][dd];
                float e2 = eiN[ty * 4 + 2][dd];
                float e3 = eiN[ty * 4 + 3][dd];
                float4 wa = *reinterpret_cast<float4*>(&w0s[d][tx * 8]);
                float4 wb = *reinterpret_cast<float4*>(&w0s[d][tx * 8 + 4]);
                float w[8] = {wa.x, wa.y, wa.z, wa.w, wb.x, wb.y, wb.z, wb.w};
#pragma unroll
                for (int j = 0; j < 8; j++) {
                    acc[0][j] += e0 * w[j];
                    acc[1][j] += e1 * w[j];
                    acc[2][j] += e2 * w[j];
                    acc[3][j] += e3 * w[j];
                }
            }
        }

        int hbase = tx * 8;
#pragma unroll
        for (int i = 0; i < 4; i++) {
            int item = i0 + ty * 4 + i;
            if (item >= NI) continue;
            float v[8];
#pragma unroll
            for (int j = 0; j < 8; j++) {
                float a = acc[i][j];
                if (h == 2) a = fmaxf(a + pb0[hbase + j], 0.f);
                v[j] = a;
            }
            __half2 h0 = __floats2half2_rn(v[0], v[1]);
            __half2 h1 = __floats2half2_rn(v[2], v[3]);
            __half2 h2c = __floats2half2_rn(v[4], v[5]);
            __half2 h3 = __floats2half2_rn(v[6], v[7]);
            uint4 pk;
            pk.x = h2u(h0); pk.y = h2u(h1); pk.z = h2u(h2c); pk.w = h2u(h3);
            __half* dst = (h < 2) ? &g_C16[h][item * NH + hbase]
                                  : &g_Cp16[item * NH + hbase];
            *reinterpret_cast<uint4*>(dst) = pk;
        }
    } else if (bx < 942) {
        float (*eu_s)[65] = reinterpret_cast<float(*)[65]>(pbuf);
        float* inv = reinterpret_cast<float*>(pbuf + 16640);
        for (int idx = tid; idx < NB * ND; idx += 256) {
            int b = idx >> 6, d = idx & 63;
            eu_s[b][d] = ue[users[b] * ND + d];
        }
        __syncthreads();
        int blk = bx - 939;
        if (blk < 2) {
            const float* W0 = (blk == 0) ? lW0 : rW0;
            const float* b0 = (blk == 0) ? lb0 : rb0;
            for (int o = tid; o < NB * NH; o += 256) {
                int b = o >> 7, h = o & 127;
                float acc = b0[h];
#pragma unroll
                for (int d = 0; d < ND; d++)
                    acc += eu_s[b][d] * W0[d * NH + h];
                g_au16[blk][o] = __float2half(acc);
            }
        } else {
            for (int b = tid; b < NB; b += 256) {
                float s = 0.f;
#pragma unroll
                for (int d = 0; d < ND; d++) { float v = eu_s[b][d]; s += v * v; }
                inv[b] = rsqrtf(fmaxf(s, 1e-12f));
            }
            __syncthreads();
            for (int o = tid; o < NB * NB; o += 256) {
                int a = o >> 6, b = o & 63;
                float s = 0.f;
#pragma unroll
                for (int d = 0; d < ND; d++)
                    s += eu_s[a][d] * eu_s[b][d];
                out_sim[o] = -(s * inv[a] * inv[b]);
            }
        }
    } else {
        int base = (bx - 942) * 1024 + tid;
#pragma unroll
        for (int j = 0; j < 4; j++) {
            int idx = base + j * 256;
            if (idx < 3 * NH * NH) {
                int h = idx / (NH * NH);
                int rem = idx - h * NH * NH;
                const float* W = (h == 0) ? lW1 : (h == 1) ? rW1 : pW1;
                g_W16[h][rem] = __float2half(W[rem]);
            }
        }
    }
}

// ---------------------------------------------------------------------------
// Work decode: tile index w -> (head, user-tile base, item base)
// ---------------------------------------------------------------------------
__device__ __forceinline__ void decode_w(int w, int& head, int& b0u, int& i0) {
    if (w < 20000) {
        head = w / 10000;
        int rem = w - head * 10000;
        b0u = (rem / 1250) * 8;
        i0 = (rem % 1250) * 16;
    } else {
        head = 2;
        b0u = 0;
        i0 = (w - 20000) * 128;
    }
}

// ---------------------------------------------------------------------------
// A-tile builder: uint4 loads, fully unrolled (8 iterations / thread @256t)
// ---------------------------------------------------------------------------
__device__ __forceinline__ void build_A(__half* __restrict__ dst, int head,
                                        int b0u, int i0, int tid)
{
    const __half2 z2 = __floats2half2_rn(0.f, 0.f);
    if (head < 2) {
#pragma unroll
        for (int it = 0; it < 8; it++) {
            int idx = tid + it * 256;
            int r = idx >> 4;
            int kc = (idx & 15) << 3;
            int b = b0u + (r & 7);
            int ii = i0 + (r >> 3);
            uint4 cv = *reinterpret_cast<const uint4*>(&g_C16[head][ii * NH + kc]);
            uint4 av = *reinterpret_cast<const uint4*>(&g_au16[head][b * NH + kc]);
            uint4 p;
            p.x = h2u(__hmax2(__hadd2(u2h(cv.x), u2h(av.x)), z2));
            p.y = h2u(__hmax2(__hadd2(u2h(cv.y), u2h(av.y)), z2));
            p.z = h2u(__hmax2(__hadd2(u2h(cv.z), u2h(av.z)), z2));
            p.w = h2u(__hmax2(__hadd2(u2h(cv.w), u2h(av.w)), z2));
            *reinterpret_cast<uint4*>(&dst[r * 136 + kc]) = p;
        }
    } else {
#pragma unroll
        for (int it = 0; it < 8; it++) {
            int idx = tid + it * 256;
            int r = idx >> 4;
            int kc = (idx & 15) << 3;
            int ii = i0 + r;
            uint4 p = (ii < NI)
                ? *reinterpret_cast<const uint4*>(&g_Cp16[ii * NH + kc])
                : make_uint4(0u, 0u, 0u, 0u);
            *reinterpret_cast<uint4*>(&dst[r * 136 + kc]) = p;
        }
    }
}

// ---------------------------------------------------------------------------
// main_mma: persistent 256-thread blocks (2 CTA/SM), 8 warps as (2M x 4N),
// warp tile 64x32. B/params resident per head; A double-buffered; 1 sync/tile.
// ---------------------------------------------------------------------------
__global__ __launch_bounds__(256, 2) void main_mma(
    const float* __restrict__ lb1, const float* __restrict__ lW2, const float* __restrict__ lb2,
    const float* __restrict__ rb1, const float* __restrict__ rW2, const float* __restrict__ rb2,
    const float* __restrict__ pb1, const float* __restrict__ pW2, const float* __restrict__ pb2,
    float* __restrict__ out)
{
    extern __shared__ char dynsmem[];
    __half* As = reinterpret_cast<__half*>(dynsmem);          // 2 x (128*136)
    __half* Bs = As + 2 * 128 * 136;                          // 128*136
    float* zpart = reinterpret_cast<float*>(Bs + 128 * 136);  // 2 x 512
    float* b1s = zpart + 1024;
    float* w2s = b1s + 128;

    int tid = threadIdx.x;
    int warp = tid >> 5, lane = tid & 31;
    int warpM = warp >> 2, warpN = warp & 3;
    int m_base = warpM * 64, n_base = warpN * 32;
    int bid = blockIdx.x;

    int cbase = N_WORK / GRID_MAIN;
    int crem  = N_WORK % GRID_MAIN;
    int w0 = bid * cbase + min(bid, crem);
    int w1 = w0 + cbase + (bid < crem ? 1 : 0);

    int head, b0u, i0;
    decode_w(w0, head, b0u, i0);

    // ldsm geometry
    int arow = lane & 15;
    int acol_off = (lane >> 4) << 3;
    int g = lane >> 2, tq = lane & 3;
    int bgrp = lane >> 3;
    int brow_off = ((bgrp & 1) << 3) + (lane & 7);
    int bcol_off = (bgrp >> 1) << 3;

    // ---- Load head state (Bs, b1s, w2s, b2v) ----
    float b2v = sel3(head, lb2, rb2, pb2)[0];
    if (tid < 128) {
        b1s[tid] = sel3(head, lb1, rb1, pb1)[tid];
        w2s[tid] = sel3(head, lW2, rW2, pW2)[tid];
    }
    {
        const __half* Wsrc = g_W16[head];
#pragma unroll
        for (int it = 0; it < 8; it++) {
            int idx = tid + it * 256;
            int kk = idx >> 4;
            int n8 = (idx & 15) << 3;
            uint4 v = *reinterpret_cast<const uint4*>(&Wsrc[kk * NH + n8]);
            *reinterpret_cast<uint4*>(&Bs[kk * 136 + n8]) = v;
        }
    }
    build_A(As, head, b0u, i0, tid);
    __syncthreads();

    int p = 0;
    for (int w = w0; w < w1; w++) {
        const __half* Ab = As + p * (128 * 136);

        float acc[4][4][4];
#pragma unroll
        for (int f = 0; f < 4; f++)
#pragma unroll
            for (int g2 = 0; g2 < 4; g2++)
#pragma unroll
                for (int q = 0; q < 4; q++) acc[f][g2][q] = 0.f;

        // ---- 8 k-steps of m16n8k16: B first, then A (overlap A under MMAs) ----
#pragma unroll
        for (int ks = 0; ks < 8; ks++) {
            uint32_t bfr[4][2];
            int brow = (ks << 4) + brow_off;
#pragma unroll
            for (int pr = 0; pr < 2; pr++) {
                uint32_t tmp[4];
                int bcol = n_base + (pr << 4) + bcol_off;
                ldsm_x4_trans(tmp, smem_u32(&Bs[brow * 136 + bcol]));
                bfr[2 * pr][0] = tmp[0]; bfr[2 * pr][1] = tmp[1];
                bfr[2 * pr + 1][0] = tmp[2]; bfr[2 * pr + 1][1] = tmp[3];
            }
            int kA = (ks << 4) + acol_off;
            uint32_t afr[4][4];
#pragma unroll
            for (int f = 0; f < 4; f++)
                ldsm_x4(afr[f], smem_u32(&Ab[(m_base + f * 16 + arow) * 136 + kA]));
#pragma unroll
            for (int f = 0; f < 4; f++)
#pragma unroll
                for (int g2 = 0; g2 < 4; g2++)
                    mma_fp16(acc[f][g2], afr[f], bfr[g2], acc[f][g2]);
        }

        // ---- Prefetch-build next A into other buffer ----
        bool have_next = (w + 1 < w1);
        int nhead = head, nb0u = b0u, ni0 = i0;
        if (have_next) {
            decode_w(w + 1, nhead, nb0u, ni0);
            build_A(As + (p ^ 1) * (128 * 136), nhead, nb0u, ni0, tid);
        }

        // ---- Epilogue partials ----
        float* zp = zpart + p * 512;
#pragma unroll
        for (int f = 0; f < 4; f++) {
            float z0 = 0.f, z1 = 0.f;
#pragma unroll
            for (int nf = 0; nf < 4; nf++) {
                int col = n_base + nf * 8 + tq * 2;
                float b10 = b1s[col], b11 = b1s[col + 1];
                float ww0 = w2s[col], ww1 = w2s[col + 1];
                z0 += fmaxf(acc[f][nf][0] + b10, 0.f) * ww0 + fmaxf(acc[f][nf][1] + b11, 0.f) * ww1;
                z1 += fmaxf(acc[f][nf][2] + b10, 0.f) * ww0 + fmaxf(acc[f][nf][3] + b11, 0.f) * ww1;
            }
            z0 += __shfl_xor_sync(0xffffffffu, z0, 1);
            z0 += __shfl_xor_sync(0xffffffffu, z0, 2);
            z1 += __shfl_xor_sync(0xffffffffu, z1, 1);
            z1 += __shfl_xor_sync(0xffffffffu, z1, 2);
            if (tq == 0) {
                zp[warpN * 128 + m_base + f * 16 + g] = z0;
                zp[warpN * 128 + m_base + f * 16 + g + 8] = z1;
            }
        }
        __syncthreads();   // zpart ready + next A ready; all MMA(w) done

        // ---- Final stores for w ----
        if (tid < 128) {
            if (head < 2) {
                int r = ((tid & 15) << 3) | (tid >> 4);
                float z = zp[r] + zp[128 + r] + zp[256 + r] + zp[384 + r] + b2v;
                float s = 1.f / (1.f + __expf(-z));
                int b = b0u + (tid >> 4);
                int i = i0 + (tid & 15);
                out[(head ? OFF_RATED : OFF_LIKES) + b * NI + i] = s;
            } else {
                float z = zp[tid] + zp[128 + tid] + zp[256 + tid] + zp[384 + tid] + b2v;
                float s = 1.f / (1.f + __expf(-z));
                int i = i0 + tid;
                if (i < NI) out[OFF_POP + i] = s;
            }
        }

        // ---- Head boundary: reload Bs/b1s/w2s/b2v (2 blocks globally) ----
        if (have_next && nhead != head) {
            b2v = sel3(nhead, lb2, rb2, pb2)[0];
            if (tid < 128) {
                b1s[tid] = sel3(nhead, lb1, rb1, pb1)[tid];
                w2s[tid] = sel3(nhead, lW2, rW2, pW2)[tid];
            }
            const __half* Wsrc = g_W16[nhead];
#pragma unroll
            for (int it = 0; it < 8; it++) {
                int idx = tid + it * 256;
                int kk = idx >> 4;
                int n8 = (idx & 15) << 3;
                uint4 v = *reinterpret_cast<const uint4*>(&Wsrc[kk * NH + n8]);
                *reinterpret_cast<uint4*>(&Bs[kk * 136 + n8]) = v;
            }
            __syncthreads();   // Bs/b1s/w2s ready before MMA(w+1)
        }

        head = nhead; b0u = nb0u; i0 = ni0;
        p ^= 1;
    }
}

// ---------------------------------------------------------------------------
extern "C" void kernel_launch(void* const* d_in, const int* in_sizes, int n_in,
                              void* d_out, int out_size)
{
    const int*   users = (const int*)  d_in[0];
    const float* ue    = (const float*)d_in[1];
    const float* ie    = (const float*)d_in[2];
    const float* lW0 = (const float*)d_in[3];
    const float* lb0 = (const float*)d_in[4];
    const float* lW1 = (const float*)d_in[5];
    const float* lb1 = (const float*)d_in[6];
    const float* lW2 = (const float*)d_in[7];
    const float* lb2 = (const float*)d_in[8];
    const float* rW0 = (const float*)d_in[9];
    const float* rb0 = (const float*)d_in[10];
    const float* rW1 = (const float*)d_in[11];
    const float* rb1 = (const float*)d_in[12];
    const float* rW2 = (const float*)d_in[13];
    const float* rb2 = (const float*)d_in[14];
    const float* pW0 = (const float*)d_in[15];
    const float* pb0 = (const float*)d_in[16];
    const float* pW1 = (const float*)d_in[17];
    const float* pb1 = (const float*)d_in[18];
    const float* pW2 = (const float*)d_in[19];
    const float* pb2 = (const float*)d_in[20];
    float* out = (float*)d_out;

    cudaFuncSetAttribute(main_mma, cudaFuncAttributeMaxDynamicSharedMemorySize,
                         SMEM_BYTES);

    prep_all<<<990, 256>>>(users, ue, ie,
                           lW0, lb0, rW0, rb0, pW0, pb0,
                           lW1, rW1, pW1,
                           out + OFF_SIM);
    main_mma<<<GRID_MAIN, 256, SMEM_BYTES>>>(lb1, lW2, lb2,
                                             rb1, rW2, rb2,
                                             pb1, pW2, pb2,
                                             out);
}